// round 8
// baseline (speedup 1.0000x reference)
#include <cuda_runtime.h>
#include <cuda_bf16.h>
#include <cstdint>

// yolo_v3 detection head:
//   in : x [B, 255, 64, 64] f32, anchors [3,2] f32
//   out: [B, 4096*3, 85] f32
// out[b, s*255 + r] = f(x[b, r, s]),  r = a*85+d:
//   d==0: (sigmoid(v) + s%64) * 8
//   d==1: (sigmoid(v) + s/64) * 8
//   d==2,3: exp(v) * anchors[a][d-2]   (stride factors cancel)
//   d>=4: sigmoid(v)
// sigmoid via tanh.approx (1 MUFU): sig(v) = 0.5*tanh(0.5v) + 0.5

#define S_DIM 64
#define WH    4096
#define NA    3
#define ND    85
#define NC    255
#define TS    16
#define NBUF  2
#define NTHREADS 256
#define NITEMS (NC * (TS / 4))       // 1020 float4 items per tile
#define TILE_ELEMS (TS * NC)         // 4080
#define TILE_BYTES (TILE_ELEMS * 4)  // 16320
#define TILES_PER_IMG (WH / TS)      // 256
#define NBLOCKS 888                  // ~6 blocks/SM, grid-stride persistent

__device__ __forceinline__ float fast_sigmoid(float v) {
    float t;
    asm("tanh.approx.f32 %0, %1;" : "=f"(t) : "f"(0.5f * v));
    return fmaf(0.5f, t, 0.5f);
}

__global__ __launch_bounds__(NTHREADS, 6)
void yolo_head_kernel(const float* __restrict__ x,
                      const float* __restrict__ anchors,
                      float* __restrict__ out,
                      int ntiles)
{
    __shared__ __align__(16) float tile[NBUF][TILE_ELEMS];

    const int tid = threadIdx.x;

    // ---- Per-thread item parameters (tile-invariant), k = 0..3 ----
    // item i = tid + k*256 -> c = i>>2 (channel), q = i&3 (float4 in row)
    float p_scale[4];     // sigmoid scale (8 or 1) or anchor (exp path)
    float p_ob0[4];       // 8*4q for d==0, else 0
    float p_ostep[4];     // 8 (d==0) else 0
    int   p_mode[4];      // 0 = sigmoid, 1 = exp, 2 = sig+x-grid, 3 = sig+y-grid
    bool  p_act[4];
    #pragma unroll
    for (int k = 0; k < 4; k++) {
        int i = tid + k * NTHREADS;
        p_act[k] = (i < NITEMS);
        int c = i >> 2, q = i & 3;
        if (c > NC - 1) c = NC - 1;
        int a = (c >= 2 * ND) ? 2 : (c >= ND ? 1 : 0);
        int d = c - a * ND;
        p_scale[k] = 1.0f; p_ob0[k] = 0.0f; p_ostep[k] = 0.0f; p_mode[k] = 0;
        if (d == 0)      { p_mode[k] = 2; p_scale[k] = 8.0f; p_ob0[k] = 32.0f * q; p_ostep[k] = 8.0f; }
        else if (d == 1) { p_mode[k] = 3; p_scale[k] = 8.0f; }
        else if (d < 4)  { p_mode[k] = 1; p_scale[k] = __ldg(&anchors[a * 2 + (d - 2)]); }
    }

    int buf = 0;
    for (int tidx = blockIdx.x; tidx < ntiles; tidx += NBLOCKS) {
        const int b  = tidx >> 8;            // TILES_PER_IMG = 256
        const int t  = tidx & (TILES_PER_IMG - 1);
        const int s0 = t * TS;
        const float fx8 = 8.0f * (float)(s0 & (S_DIM - 1));
        const float fy8 = 8.0f * (float)(s0 >> 6);

        // Reclaim this buffer: the DMA committed NBUF iterations ago is done
        // once at most NBUF-1 groups remain pending.
        if (tid == 0)
            asm volatile("cp.async.bulk.wait_group 1;" ::: "memory");
        __syncthreads();

        const float4* __restrict__ xin =
            reinterpret_cast<const float4*>(x + (size_t)b * NC * WH + s0);
        float* __restrict__ tb = tile[buf];

        #pragma unroll
        for (int k = 0; k < 4; k++) {
            int i = tid + k * NTHREADS;
            if (p_act[k]) {
                int c = i >> 2, q = i & 3;
                float4 v = xin[c * (WH / 4) + q];
                float vv[4] = {v.x, v.y, v.z, v.w};
                float off = 0.0f;
                if (p_mode[k] == 2) off = fx8 + p_ob0[k];
                else if (p_mode[k] == 3) off = fy8;
                float* dst = &tb[(q * 4) * NC + c];
                #pragma unroll
                for (int j = 0; j < 4; j++) {
                    float res;
                    if (p_mode[k] == 1) {
                        res = __expf(vv[j]) * p_scale[k];
                    } else {
                        res = fmaf(fast_sigmoid(vv[j]), p_scale[k],
                                   fmaf(p_ostep[k], (float)j, off));
                    }
                    dst[j * NC] = res;
                }
            }
        }

        __syncthreads();

        if (tid == 0) {
            asm volatile("fence.proxy.async.shared::cta;" ::: "memory");
            float* gdst = out + (size_t)b * WH * NC + (size_t)s0 * NC;
            uint32_t saddr;
            asm("{ .reg .u64 t; cvta.to.shared.u64 t, %1; cvt.u32.u64 %0, t; }"
                : "=r"(saddr) : "l"(tb));
            uint32_t nbytes = TILE_BYTES;
            asm volatile(
                "cp.async.bulk.global.shared::cta.bulk_group [%0], [%1], %2;"
                :: "l"(gdst), "r"(saddr), "r"(nbytes) : "memory");
            asm volatile("cp.async.bulk.commit_group;" ::: "memory");
        }
        buf ^= 1;
    }

    // Drain all pending DMAs before smem is released.
    if (tid == 0)
        asm volatile("cp.async.bulk.wait_group 0;" ::: "memory");
}

extern "C" void kernel_launch(void* const* d_in, const int* in_sizes, int n_in,
                              void* d_out, int out_size)
{
    const float* x       = (const float*)d_in[0];
    const float* anchors = (const float*)d_in[1];
    float* out           = (float*)d_out;

    int B = in_sizes[0] / (NC * WH);
    int ntiles = B * TILES_PER_IMG;
    yolo_head_kernel<<<NBLOCKS, NTHREADS>>>(x, anchors, out, ntiles);
}